// round 14
// baseline (speedup 1.0000x reference)
#include <cuda_runtime.h>
#include <cuda_fp16.h>
#include <cstdint>

#define Tn 8192
#define Hn 1024
#define In 2816
#define En 8
#define MAXP 17408  // 16384 pairs + per-expert 128-alignment padding

// ------------------- device scratch (no allocations allowed) -----------------
__device__ int    g_cnt[En];
__device__ int    g_cur[En];
__device__ int    g_off[En + 1];
__device__ int    g_eid[Tn * 2];
__device__ float  g_ew[Tn * 2];
__device__ int    g_tok[MAXP];
__device__ float  g_wt[MAXP];
__device__ int    g_slots[Tn * 2];
__device__ __half g_xh[(size_t)MAXP * Hn];    // gathered x rows, fp16
__device__ __half g_hbh[(size_t)MAXP * In];   // silu(gate)*up, fp16
__device__ __half g_poh[(size_t)MAXP * Hn];   // per-pair weighted out, fp16

// ------------------- helpers -------------------------------------------------
__device__ __forceinline__ uint32_t smem_u32(const void* p) {
    uint32_t a;
    asm("{ .reg .u64 t; cvta.to.shared.u64 t, %1; cvt.u32.u64 %0, t; }" : "=r"(a) : "l"(p));
    return a;
}
__device__ __forceinline__ void cp16(uint32_t saddr, const void* gsrc) {
    asm volatile("cp.async.cg.shared.global [%0], [%1], 16;\n" :: "r"(saddr), "l"(gsrc));
}
// fp16 m16n8k16 mma, fp32 accumulate
__device__ __forceinline__ void mma16(float* c, const uint32_t* a, const uint32_t* b) {
    asm volatile(
        "mma.sync.aligned.m16n8k16.row.col.f32.f16.f16.f32 "
        "{%0,%1,%2,%3}, {%4,%5,%6,%7}, {%8,%9}, {%0,%1,%2,%3};\n"
        : "+f"(c[0]), "+f"(c[1]), "+f"(c[2]), "+f"(c[3])
        : "r"(a[0]), "r"(a[1]), "r"(a[2]), "r"(a[3]), "r"(b[0]), "r"(b[1]));
}
__device__ __forceinline__ void ldm4(uint32_t* r, uint32_t addr) {
    asm volatile("ldmatrix.sync.aligned.m8n8.x4.shared.b16 {%0,%1,%2,%3}, [%4];"
                 : "=r"(r[0]), "=r"(r[1]), "=r"(r[2]), "=r"(r[3]) : "r"(addr));
}
__device__ __forceinline__ uint32_t h2u(__half2 h) { return *(uint32_t*)&h; }

// convert 4 fp32 -> 4 fp16 and store 8 bytes to smem
__device__ __forceinline__ void sts_h4(uint32_t addr, float4 v) {
    uint32_t lo = h2u(__floats2half2_rn(v.x, v.y));
    uint32_t hi = h2u(__floats2half2_rn(v.z, v.w));
    asm volatile("st.shared.v2.b32 [%0], {%1,%2};" :: "r"(addr), "r"(lo), "r"(hi) : "memory");
}

// smem: K-chunk = 64 halves (128 B/row), pitch 144 B.
// Stage: A 128x144 = 18,432 B; B 256x144 = 36,864 B -> 55,296 B. 3 stages.
static constexpr int ROWP_B = 144;
static constexpr int STG_B  = 55296;
static constexpr int BOFF_B = 18432;
static constexpr int SMEM_BYTES = STG_B * 3;  // 165,888 B

// ------------------- kernel: reset per-call state -----------------------------
__global__ void k_init() {
    int i = blockIdx.x * blockDim.x + threadIdx.x;
    if (i < En) { g_cnt[i] = 0; g_cur[i] = 0; }
    for (int s = i; s < MAXP; s += gridDim.x * blockDim.x) {
        g_tok[s] = -1;
        g_wt[s] = 0.0f;
    }
}

// ------------------- kernel: router ------------------------------------------
__global__ void k_router(const float* __restrict__ logits) {
    int t = blockIdx.x * blockDim.x + threadIdx.x;
    if (t >= Tn) return;
    float v[En];
#pragma unroll
    for (int e = 0; e < En; e++) v[e] = logits[t * En + e];
    int b0 = 0; float m0 = v[0];
#pragma unroll
    for (int e = 1; e < En; e++) if (v[e] > m0) { m0 = v[e]; b0 = e; }
    int b1 = -1; float m1 = -3.0e38f;
#pragma unroll
    for (int e = 0; e < En; e++) if (e != b0 && v[e] > m1) { m1 = v[e]; b1 = e; }
    float e1 = expf(m1 - m0);
    float inv = 1.0f / (1.0f + e1);
    g_eid[2 * t] = b0;     g_ew[2 * t] = inv;
    g_eid[2 * t + 1] = b1; g_ew[2 * t + 1] = e1 * inv;
    atomicAdd(&g_cnt[b0], 1);
    atomicAdd(&g_cnt[b1], 1);
}

// ------------------- kernel: 128-aligned offsets ------------------------------
__global__ void k_off() {
    if (threadIdx.x == 0 && blockIdx.x == 0) {
        int o = 0;
        g_off[0] = 0;
        for (int e = 0; e < En; e++) {
            o += (g_cnt[e] + 127) & ~127;
            g_off[e + 1] = o;
        }
    }
}

// ------------------- kernel: scatter ------------------------------------------
__global__ void k_scatter() {
    int t = blockIdx.x * blockDim.x + threadIdx.x;
    if (t >= Tn) return;
#pragma unroll
    for (int k = 0; k < 2; k++) {
        int e = g_eid[2 * t + k];
        int pos = atomicAdd(&g_cur[e], 1);
        int s = g_off[e] + pos;
        g_tok[s] = t;
        g_wt[s] = g_ew[2 * t + k];
        g_slots[2 * t + k] = s;
    }
}

// ------------------- kernel: gather x rows -> fp16 ----------------------------
__global__ void k_gather(const float* __restrict__ x) {
    int s = blockIdx.x;
    int tok = g_tok[s];
    uint2 pk = { 0u, 0u };
    if (tok >= 0) {
        float4 v = *(const float4*)&x[(size_t)tok * Hn + threadIdx.x * 4];
        pk.x = h2u(__floats2half2_rn(v.x, v.y));
        pk.y = h2u(__floats2half2_rn(v.z, v.w));
    }
    *(uint2*)&g_xh[(size_t)s * Hn + threadIdx.x * 4] = pk;
}

// =============================================================================
// GEMM mainloop: CTA tile M=128 x 256 B-rows, fp16 m16n8k16, K-chunk = 64.
// A (fp16 activations) via cp.async; B (fp32 weights) via LDG + in-loop
// convert + STS, interleaved with mma ksteps. 3 stages, lookahead 2, ONE
// barrier per chunk. 8 warps of 64x64.
// Loader mapping: B: r0 = tid>>4 (0..15), s4 = tid&15; rows r0+16q, q=0..15.
//                 A: rA0 = tid>>3 (0..31), sgA = tid&7; rows rA0+32q, q=0..3.
// =============================================================================

__device__ __forceinline__ int ldm_lane_off(int lane) {
    int lr = lane & 7, grp = lane >> 3;
    int rowoff = lr + (grp & 1) * 8;
    int coloff = (grp >> 1) * 8;
    return rowoff * ROWP_B + coloff * 2;
}

#define MMA_KSTEP(ks) do {                                                         \
    const int k0b = (ks) * 32;                                                     \
    uint32_t af[4][4], bf[8][2];                                                   \
    _Pragma("unroll")                                                              \
    for (int mi = 0; mi < 4; mi++)                                                 \
        ldm4(af[mi], aS + (mBase + mi * 16) * ROWP_B + k0b + loff);                \
    _Pragma("unroll")                                                              \
    for (int nj = 0; nj < 4; nj++) {                                               \
        uint32_t t4[4];                                                            \
        ldm4(t4, bS + (nBase + nj * 16) * ROWP_B + k0b + loff);                    \
        bf[nj * 2][0] = t4[0]; bf[nj * 2 + 1][0] = t4[1];                          \
        bf[nj * 2][1] = t4[2]; bf[nj * 2 + 1][1] = t4[3];                          \
    }                                                                              \
    _Pragma("unroll")                                                              \
    for (int mi = 0; mi < 4; mi++)                                                 \
        _Pragma("unroll")                                                          \
        for (int ni = 0; ni < 8; ni++) mma16(acc[mi][ni], af[mi], bf[ni]);         \
} while (0)

#define LDG_B4(b) do { if (pf) {                                                   \
    _Pragma("unroll")                                                              \
    for (int qq = 0; qq < 4; qq++) vb[qq] = *(const float4*)B_ADDR((b) + qq, i + 2); } } while (0)

#define STS_B4(b) do { if (pf) {                                                   \
    _Pragma("unroll")                                                              \
    for (int qq = 0; qq < 4; qq++)                                                 \
        sts_h4(sB0 + stl * STG_B + ((b) + qq) * 16 * ROWP_B, vb[qq]); } } while (0)

#define GEMM_MAINLOOP(NC)                                                          \
    /* prologue: chunks 0,1 into stages 0,1 */                                     \
    _Pragma("unroll")                                                              \
    for (int c = 0; c < 2; c++) {                                                  \
        _Pragma("unroll")                                                          \
        for (int q = 0; q < 4; q++)                                                \
            cp16(sA0 + c * STG_B + q * 32 * ROWP_B, pA0 + (size_t)q * 32 * strA + c * 64); \
        asm volatile("cp.async.commit_group;" ::: "memory");                       \
        _Pragma("unroll")                                                          \
        for (int q = 0; q < 16; q++) {                                             \
            float4 v = *(const float4*)B_ADDR(q, c);                               \
            sts_h4(sB0 + c * STG_B + q * 16 * ROWP_B, v);                          \
        }                                                                          \
    }                                                                              \
    for (int i = 0; i < (NC); i++) {                                               \
        const int st = i % 3;                                                      \
        const int stl = (i + 2) % 3;                                               \
        const bool pf = (i + 2) < (NC);                                            \
        asm volatile("cp.async.wait_group 1;" ::: "memory");                       \
        __syncthreads();                                                           \
        const uint32_t aS = sbA + st * STG_B;                                      \
        const uint32_t bS = sbB + st * STG_B;                                      \
        float4 vb[4];                                                              \
        LDG_B4(0);                                                                 \
        MMA_KSTEP(0);                                                              \
        STS_B4(0); LDG_B4(4);                                                      \
        MMA_KSTEP(1);                                                              \
        STS_B4(4); LDG_B4(8);                                                      \
        MMA_KSTEP(2);                                                              \
        STS_B4(8); LDG_B4(12);                                                     \
        MMA_KSTEP(3);                                                              \
        STS_B4(12);                                                                \
        if (pf) {                                                                  \
            _Pragma("unroll")                                                      \
            for (int q = 0; q < 4; q++)                                            \
                cp16(sA0 + stl * STG_B + q * 32 * ROWP_B,                          \
                     pA0 + (size_t)q * 32 * strA + (size_t)(i + 2) * 64);          \
        }                                                                          \
        asm volatile("cp.async.commit_group;" ::: "memory");                       \
    }

// =============================================================================
// GEMM1: h = silu(x W1^T) * (x W3^T). B-rows 0..127 = gate, 128..255 = up.
// Weights read fp32 directly from w13 (no fp16 scratch).
// =============================================================================
__global__ __launch_bounds__(256, 1) void k_gemm1(const float* __restrict__ w13) {
    extern __shared__ __align__(16) char smraw[];
    const int mtile = blockIdx.x, ntile = blockIdx.y;  // mtile fast (A L2-reuse)
    if (mtile * 128 >= g_off[En]) return;
    int e = 0;
#pragma unroll
    for (int i = 0; i < En; i++) if (mtile * 128 >= g_off[i + 1]) e = i + 1;
    const int n0 = ntile * 128;
    const int tid = threadIdx.x;

    const uint32_t sb = smem_u32(smraw);
    const uint32_t sbA = sb, sbB = sb + BOFF_B;

    // B loader (fp32 weights): rows r0+16q, float4 seg s4
    const int r0 = tid >> 4, s4 = tid & 15;
    const float* pBg = w13 + ((size_t)e * 2 * In + n0 + r0) * Hn + s4 * 4;
    const float* pBu = w13 + ((size_t)e * 2 * In + In + n0 + r0) * Hn + s4 * 4;
    const uint32_t sB0 = sbB + r0 * ROWP_B + s4 * 8;
#define B_ADDR(q, c) (((q) < 8 ? pBg + (size_t)(q) * 16 * Hn                       \
                               : pBu + (size_t)((q) - 8) * 16 * Hn) + (size_t)(c) * 64)

    // A loader (fp16 activations)
    const int rA0 = tid >> 3, sgA = tid & 7;
    const int strA = Hn;
    const __half* pA0 = g_xh + (size_t)(mtile * 128 + rA0) * Hn + sgA * 8;
    const uint32_t sA0 = sbA + rA0 * ROWP_B + sgA * 16;

    const int w = tid >> 5, lane = tid & 31;
    const int mBase = (w & 1) * 64, nBase = (w >> 1) * 64;
    const int qr = lane >> 2, qc = lane & 3;
    const int loff = ldm_lane_off(lane);

    float acc[4][8][4];
#pragma unroll
    for (int a = 0; a < 4; a++)
#pragma unroll
        for (int b = 0; b < 8; b++)
#pragma unroll
            for (int c = 0; c < 4; c++) acc[a][b][c] = 0.0f;

    GEMM_MAINLOOP(Hn / 64)  // 16 chunks
#undef B_ADDR

    __syncthreads();  // all warps done reading stages before sE overlay

    // ---- epilogue: gate warps stage to smem; up warps compute silu(g)*u ------
    float* sE = (float*)smraw;  // 128 x pitch-130 floats = 66,560 B (fits)
    if (nBase < 128) {
#pragma unroll
        for (int mi = 0; mi < 4; mi++)
#pragma unroll
            for (int ni = 0; ni < 8; ni++) {
                int r = mBase + mi * 16 + qr;
                int c = nBase + ni * 8 + qc * 2;
                sE[r * 130 + c] = acc[mi][ni][0];
                sE[r * 130 + c + 1] = acc[mi][ni][1];
                sE[(r + 8) * 130 + c] = acc[mi][ni][2];
                sE[(r + 8) * 130 + c + 1] = acc[mi][ni][3];
            }
    }
    __syncthreads();
    if (nBase >= 128) {
        const size_t rowBase = (size_t)mtile * 128;
#pragma unroll
        for (int mi = 0; mi < 4; mi++)
#pragma unroll
            for (int ni = 0; ni < 8; ni++) {
                int j = (nBase - 128) + ni * 8 + qc * 2;
#pragma unroll
                for (int half = 0; half < 2; half++) {
                    int r = mBase + mi * 16 + qr + half * 8;
                    float g0 = sE[r * 130 + j];
                    float g1 = sE[r * 130 + j + 1];
                    float u0 = acc[mi][ni][half * 2];
                    float u1 = acc[mi][ni][half * 2 + 1];
                    float h0 = g0 * (1.0f / (1.0f + __expf(-g0))) * u0;
                    float h1 = g1 * (1.0f / (1.0f + __expf(-g1))) * u1;
                    __half2 hv = __floats2half2_rn(h0, h1);
                    *(__half2*)&g_hbh[(rowBase + r) * In + (size_t)n0 + j] = hv;
                }
            }
    }
}

// =============================================================================
// GEMM2: po = wt * (h W2^T).  CTA tile M=128 x N=256 out cols, K = In.
// Weights read fp32 directly from w2.
// =============================================================================
__global__ __launch_bounds__(256, 1) void k_gemm2(const float* __restrict__ w2) {
    extern __shared__ __align__(16) char smraw[];
    const int ntile = blockIdx.x, mtile = blockIdx.y;  // ntile fast (w2 L2-resident)
    if (mtile * 128 >= g_off[En]) return;
    int e = 0;
#pragma unroll
    for (int i = 0; i < En; i++) if (mtile * 128 >= g_off[i + 1]) e = i + 1;
    const int n0 = ntile * 256;
    const int tid = threadIdx.x;

    const uint32_t sb = smem_u32(smraw);
    const uint32_t sbA = sb, sbB = sb + BOFF_B;

    const int r0 = tid >> 4, s4 = tid & 15;
    const float* pB0 = w2 + ((size_t)e * Hn + n0 + r0) * In + s4 * 4;
    const uint32_t sB0 = sbB + r0 * ROWP_B + s4 * 8;
#define B_ADDR(q, c) (pB0 + (size_t)(q) * 16 * In + (size_t)(c) * 64)

    const int rA0 = tid >> 3, sgA = tid & 7;
    const int strA = In;
    const __half* pA0 = g_hbh + (size_t)(mtile * 128 + rA0) * In + sgA * 8;
    const uint32_t sA0 = sbA + rA0 * ROWP_B + sgA * 16;

    const int w = tid >> 5, lane = tid & 31;
    const int mBase = (w & 1) * 64, nBase = (w >> 1) * 64;
    const int qr = lane >> 2, qc = lane & 3;
    const int loff = ldm_lane_off(lane);

    float acc[4][8][4];
#pragma unroll
    for (int a = 0; a < 4; a++)
#pragma unroll
        for (int b = 0; b < 8; b++)
#pragma unroll
            for (int c = 0; c < 4; c++) acc[a][b][c] = 0.0f;

    GEMM_MAINLOOP(In / 64)  // 44 chunks
#undef B_ADDR

    // ---- epilogue: scale by router weight, write per-pair fp16 output --------
    const size_t rowBase = (size_t)mtile * 128;
#pragma unroll
    for (int mi = 0; mi < 4; mi++) {
#pragma unroll
        for (int half = 0; half < 2; half++) {
            int r = mBase + mi * 16 + qr + half * 8;
            float wt = g_wt[rowBase + r];
#pragma unroll
            for (int ni = 0; ni < 8; ni++) {
                int c = nBase + ni * 8 + qc * 2;
                __half2 hv = __floats2half2_rn(wt * acc[mi][ni][half * 2],
                                               wt * acc[mi][ni][half * 2 + 1]);
                *(__half2*)&g_poh[(rowBase + r) * Hn + (size_t)n0 + c] = hv;
            }
        }
    }
}

// ------------------- combine: out[t] = po[slot0] + po[slot1] ------------------
__global__ void k_combine(float* __restrict__ out) {
    int t = blockIdx.x;
    int i = threadIdx.x;  // 256 threads x 4 halves
    int s0 = g_slots[2 * t], s1 = g_slots[2 * t + 1];
    uint2 pa = *(const uint2*)&g_poh[(size_t)s0 * Hn + i * 4];
    uint2 pb = *(const uint2*)&g_poh[(size_t)s1 * Hn + i * 4];
    float2 a0 = __half22float2(*(__half2*)&pa.x), a1 = __half22float2(*(__half2*)&pa.y);
    float2 b0 = __half22float2(*(__half2*)&pb.x), b1 = __half22float2(*(__half2*)&pb.y);
    float4 o;
    o.x = a0.x + b0.x; o.y = a0.y + b0.y; o.z = a1.x + b1.x; o.w = a1.y + b1.y;
    *(float4*)&out[(size_t)t * Hn + i * 4] = o;
}

// ------------------- launcher -------------------------------------------------
extern "C" void kernel_launch(void* const* d_in, const int* in_sizes, int n_in,
                              void* d_out, int out_size) {
    const float* x      = (const float*)d_in[0];
    const float* logits = (const float*)d_in[1];
    const float* w13    = (const float*)d_in[2];
    const float* w2     = (const float*)d_in[3];
    float* out = (float*)d_out;

    cudaFuncSetAttribute(k_gemm1, cudaFuncAttributeMaxDynamicSharedMemorySize, SMEM_BYTES);
    cudaFuncSetAttribute(k_gemm2, cudaFuncAttributeMaxDynamicSharedMemorySize, SMEM_BYTES);

    k_init<<<68, 256>>>();
    k_router<<<Tn / 256, 256>>>(logits);
    k_off<<<1, 32>>>();
    k_scatter<<<Tn / 256, 256>>>();
    k_gather<<<MAXP, 256>>>(x);
    k_gemm1<<<dim3(MAXP / 128, In / 128), 256, SMEM_BYTES>>>(w13);  // (136, 22)
    k_gemm2<<<dim3(Hn / 256, MAXP / 128), 256, SMEM_BYTES>>>(w2);   // (4, 136)
    k_combine<<<Tn, 256>>>(out);
}

// round 15
// speedup vs baseline: 1.1814x; 1.1814x over previous
#include <cuda_runtime.h>
#include <cuda_fp16.h>
#include <cstdint>

#define Tn 8192
#define Hn 1024
#define In 2816
#define En 8
#define MAXP 17408  // 16384 pairs + per-expert 128-alignment padding

// ------------------- device scratch (no allocations allowed) -----------------
__device__ int    g_cnt[En];
__device__ int    g_cur[En];
__device__ int    g_off[En + 1];
__device__ int    g_eid[Tn * 2];
__device__ float  g_ew[Tn * 2];
__device__ int    g_tok[MAXP];
__device__ float  g_wt[MAXP];
__device__ int    g_slots[Tn * 2];
__device__ __half g_xh[(size_t)MAXP * Hn];           // gathered x rows, fp16
__device__ __half g_hbh[(size_t)MAXP * In];          // silu(gate)*up, fp16
__device__ __half g_poh[(size_t)MAXP * Hn];          // per-pair weighted out, fp16
__device__ __half g_w13h[(size_t)En * 2 * In * Hn];  // fp16 w13 (92MB)
__device__ __half g_w2h[(size_t)En * Hn * In];       // fp16 w2  (46MB)

// ------------------- helpers -------------------------------------------------
__device__ __forceinline__ uint32_t smem_u32(const void* p) {
    uint32_t a;
    asm("{ .reg .u64 t; cvta.to.shared.u64 t, %1; cvt.u32.u64 %0, t; }" : "=r"(a) : "l"(p));
    return a;
}
__device__ __forceinline__ void cp16(uint32_t saddr, const void* gsrc) {
    asm volatile("cp.async.cg.shared.global [%0], [%1], 16;\n" :: "r"(saddr), "l"(gsrc));
}
// fp16 m16n8k16 mma, fp32 accumulate
__device__ __forceinline__ void mma16(float* c, const uint32_t* a, const uint32_t* b) {
    asm volatile(
        "mma.sync.aligned.m16n8k16.row.col.f32.f16.f16.f32 "
        "{%0,%1,%2,%3}, {%4,%5,%6,%7}, {%8,%9}, {%0,%1,%2,%3};\n"
        : "+f"(c[0]), "+f"(c[1]), "+f"(c[2]), "+f"(c[3])
        : "r"(a[0]), "r"(a[1]), "r"(a[2]), "r"(a[3]), "r"(b[0]), "r"(b[1]));
}
__device__ __forceinline__ void ldm4(uint32_t* r, uint32_t addr) {
    asm volatile("ldmatrix.sync.aligned.m8n8.x4.shared.b16 {%0,%1,%2,%3}, [%4];"
                 : "=r"(r[0]), "=r"(r[1]), "=r"(r[2]), "=r"(r[3]) : "r"(addr));
}
__device__ __forceinline__ uint32_t h2u(__half2 h) { return *(uint32_t*)&h; }

// smem layout: K-chunk = 128 halves (256 B/row), pitch 136 halves (272 B/row).
// Stage: A 128x272B = 34,816 B; B 256x272B = 69,632 B -> 104,448 B.
static constexpr int ROWP_B = 272;              // row pitch bytes
static constexpr int STG_B  = 104448;           // bytes per stage
static constexpr int BOFF_B = 34816;            // B offset within stage
static constexpr int SMEM_BYTES = STG_B * 2;    // 208,896 B (2 stages)

// ------------------- kernels: weights -> fp16 (forked streams) ----------------
__global__ void k_cvtw13(const float* __restrict__ w13) {
    const long N1 = (long)En * 2 * In * Hn / 4;
    const long stride = (long)gridDim.x * blockDim.x;
    for (long i = (long)blockIdx.x * blockDim.x + threadIdx.x; i < N1; i += stride) {
        float4 v = ((const float4*)w13)[i];
        uint2 pk;
        pk.x = h2u(__floats2half2_rn(v.x, v.y));
        pk.y = h2u(__floats2half2_rn(v.z, v.w));
        ((uint2*)g_w13h)[i] = pk;
    }
}
__global__ void k_cvtw2(const float* __restrict__ w2) {
    const long N2 = (long)En * Hn * In / 4;
    const long stride = (long)gridDim.x * blockDim.x;
    for (long i = (long)blockIdx.x * blockDim.x + threadIdx.x; i < N2; i += stride) {
        float4 v = ((const float4*)w2)[i];
        uint2 pk;
        pk.x = h2u(__floats2half2_rn(v.x, v.y));
        pk.y = h2u(__floats2half2_rn(v.z, v.w));
        ((uint2*)g_w2h)[i] = pk;
    }
}

// ------------------- kernel: reset per-call state -----------------------------
__global__ void k_init() {
    int i = blockIdx.x * blockDim.x + threadIdx.x;
    if (i < En) { g_cnt[i] = 0; g_cur[i] = 0; }
    for (int s = i; s < MAXP; s += gridDim.x * blockDim.x) {
        g_tok[s] = -1;
        g_wt[s] = 0.0f;
    }
}

// ------------------- kernel: router ------------------------------------------
__global__ void k_router(const float* __restrict__ logits) {
    int t = blockIdx.x * blockDim.x + threadIdx.x;
    if (t >= Tn) return;
    float v[En];
#pragma unroll
    for (int e = 0; e < En; e++) v[e] = logits[t * En + e];
    int b0 = 0; float m0 = v[0];
#pragma unroll
    for (int e = 1; e < En; e++) if (v[e] > m0) { m0 = v[e]; b0 = e; }
    int b1 = -1; float m1 = -3.0e38f;
#pragma unroll
    for (int e = 0; e < En; e++) if (e != b0 && v[e] > m1) { m1 = v[e]; b1 = e; }
    float e1 = expf(m1 - m0);
    float inv = 1.0f / (1.0f + e1);
    g_eid[2 * t] = b0;     g_ew[2 * t] = inv;
    g_eid[2 * t + 1] = b1; g_ew[2 * t + 1] = e1 * inv;
    atomicAdd(&g_cnt[b0], 1);
    atomicAdd(&g_cnt[b1], 1);
}

// ------------------- kernel: 128-aligned offsets ------------------------------
__global__ void k_off() {
    if (threadIdx.x == 0 && blockIdx.x == 0) {
        int o = 0;
        g_off[0] = 0;
        for (int e = 0; e < En; e++) {
            o += (g_cnt[e] + 127) & ~127;
            g_off[e + 1] = o;
        }
    }
}

// ------------------- kernel: scatter ------------------------------------------
__global__ void k_scatter() {
    int t = blockIdx.x * blockDim.x + threadIdx.x;
    if (t >= Tn) return;
#pragma unroll
    for (int k = 0; k < 2; k++) {
        int e = g_eid[2 * t + k];
        int pos = atomicAdd(&g_cur[e], 1);
        int s = g_off[e] + pos;
        g_tok[s] = t;
        g_wt[s] = g_ew[2 * t + k];
        g_slots[2 * t + k] = s;
    }
}

// ------------------- kernel: gather x rows -> fp16 ----------------------------
__global__ void k_gather(const float* __restrict__ x) {
    int s = blockIdx.x;
    int tok = g_tok[s];
    uint2 pk = { 0u, 0u };
    if (tok >= 0) {
        float4 v = *(const float4*)&x[(size_t)tok * Hn + threadIdx.x * 4];
        pk.x = h2u(__floats2half2_rn(v.x, v.y));
        pk.y = h2u(__floats2half2_rn(v.z, v.w));
    }
    *(uint2*)&g_xh[(size_t)s * Hn + threadIdx.x * 4] = pk;
}

// =============================================================================
// GEMM mainloop: CTA tile M=128 x 256 B-rows, fp16 m16n8k16.
// K-chunk = 128 halves (256 B/row), pitch-136 smem rows, 2-stage cp.async
// pipeline (lookahead 1), ldmatrix fragment loads, 8 warps of 64x64.
// =============================================================================

__device__ __forceinline__ int ldm_lane_off(int lane) {
    int lr = lane & 7, grp = lane >> 3;
    int rowoff = lr + (grp & 1) * 8;
    int coloff = (grp >> 1) * 8;
    return rowoff * ROWP_B + coloff * 2;
}

#define LOAD_CHUNK(c, st) do {                                                     \
    const uint32_t _sA = sA0 + (st) * STG_B;                                       \
    const uint32_t _sB = sB0 + (st) * STG_B;                                       \
    _Pragma("unroll")                                                              \
    for (int q = 0; q < 8; q++)                                                    \
        cp16(_sA + q * 16 * ROWP_B, pA0 + (size_t)q * 16 * strA + (c) * 128);      \
    _Pragma("unroll")                                                              \
    for (int q = 0; q < 16; q++)                                                   \
        cp16(_sB + q * 16 * ROWP_B, B_ADDR(q) + (c) * 128);                        \
    asm volatile("cp.async.commit_group;" ::: "memory");                           \
} while (0)

#define GEMM_MAINLOOP(NC)                                                          \
    LOAD_CHUNK(0, 0);                                                              \
    LOAD_CHUNK(1, 1);                                                              \
    for (int i = 0; i < (NC); i++) {                                               \
        const int st = i & 1;                                                      \
        asm volatile("cp.async.wait_group 1;" ::: "memory");                       \
        __syncthreads();                                                           \
        const uint32_t aS = sbA + st * STG_B;                                      \
        const uint32_t bS = sbB + st * STG_B;                                      \
        _Pragma("unroll")                                                          \
        for (int ks = 0; ks < 8; ks++) {                                           \
            const int k0b = ks * 32;                                               \
            uint32_t af[4][4], bf[8][2];                                           \
            _Pragma("unroll")                                                      \
            for (int mi = 0; mi < 4; mi++)                                         \
                ldm4(af[mi], aS + (mBase + mi * 16) * ROWP_B + k0b + loff);        \
            _Pragma("unroll")                                                      \
            for (int nj = 0; nj < 4; nj++) {                                       \
                uint32_t t4[4];                                                    \
                ldm4(t4, bS + (nBase + nj * 16) * ROWP_B + k0b + loff);            \
                bf[nj * 2][0] = t4[0]; bf[nj * 2 + 1][0] = t4[1];                  \
                bf[nj * 2][1] = t4[2]; bf[nj * 2 + 1][1] = t4[3];                  \
            }                                                                      \
            _Pragma("unroll")                                                      \
            for (int mi = 0; mi < 4; mi++)                                         \
                _Pragma("unroll")                                                  \
                for (int ni = 0; ni < 8; ni++) mma16(acc[mi][ni], af[mi], bf[ni]); \
        }                                                                          \
        __syncthreads();                                                           \
        if (i + 2 < (NC)) LOAD_CHUNK(i + 2, st);                                   \
        else asm volatile("cp.async.commit_group;" ::: "memory");                  \
    }

// =============================================================================
// GEMM1: h = silu(x W1^T) * (x W3^T). B-rows 0..127 = gate, 128..255 = up.
// =============================================================================
__global__ __launch_bounds__(256, 1) void k_gemm1() {
    extern __shared__ __align__(16) char smraw[];
    const int mtile = blockIdx.x, ntile = blockIdx.y;  // mtile fast (A L2-reuse)
    if (mtile * 128 >= g_off[En]) return;
    int e = 0;
#pragma unroll
    for (int i = 0; i < En; i++) if (mtile * 128 >= g_off[i + 1]) e = i + 1;
    const int n0 = ntile * 128;
    const int tid = threadIdx.x;

    const uint32_t sb = smem_u32(smraw);
    const uint32_t sbA = sb, sbB = sb + BOFF_B;

    // loader bases: r0 = tid>>4 (0..15), sg = tid&15
    const int r0 = tid >> 4, sg = tid & 15;
    const int strA = Hn;  // halves per A row
    const __half* pA0 = g_xh + (size_t)(mtile * 128 + r0) * Hn + sg * 8;
    const __half* pBg = g_w13h + ((size_t)e * 2 * In + n0 + r0) * Hn + sg * 8;
    const __half* pBu = g_w13h + ((size_t)e * 2 * In + In + n0 + r0) * Hn + sg * 8;
    const uint32_t sA0 = sbA + r0 * ROWP_B + sg * 16;
    const uint32_t sB0 = sbB + r0 * ROWP_B + sg * 16;
#define B_ADDR(q) ((q) < 8 ? (pBg + (size_t)(q) * 16 * Hn) : (pBu + (size_t)((q) - 8) * 16 * Hn))

    const int w = tid >> 5, lane = tid & 31;
    const int mBase = (w & 1) * 64, nBase = (w >> 1) * 64;
    const int qr = lane >> 2, qc = lane & 3;
    const int loff = ldm_lane_off(lane);

    float acc[4][8][4];
#pragma unroll
    for (int a = 0; a < 4; a++)
#pragma unroll
        for (int b = 0; b < 8; b++)
#pragma unroll
            for (int c = 0; c < 4; c++) acc[a][b][c] = 0.0f;

    GEMM_MAINLOOP(Hn / 128)  // 8 chunks
#undef B_ADDR

    // ---- epilogue: gate warps stage to smem; up warps compute silu(g)*u ------
    float* sE = (float*)smraw;  // 128 x pitch-130 floats = 66,560 B (fits)
    if (nBase < 128) {
#pragma unroll
        for (int mi = 0; mi < 4; mi++)
#pragma unroll
            for (int ni = 0; ni < 8; ni++) {
                int r = mBase + mi * 16 + qr;
                int c = nBase + ni * 8 + qc * 2;
                sE[r * 130 + c] = acc[mi][ni][0];
                sE[r * 130 + c + 1] = acc[mi][ni][1];
                sE[(r + 8) * 130 + c] = acc[mi][ni][2];
                sE[(r + 8) * 130 + c + 1] = acc[mi][ni][3];
            }
    }
    __syncthreads();
    if (nBase >= 128) {
        const size_t rowBase = (size_t)mtile * 128;
#pragma unroll
        for (int mi = 0; mi < 4; mi++)
#pragma unroll
            for (int ni = 0; ni < 8; ni++) {
                int j = (nBase - 128) + ni * 8 + qc * 2;
#pragma unroll
                for (int half = 0; half < 2; half++) {
                    int r = mBase + mi * 16 + qr + half * 8;
                    float g0 = sE[r * 130 + j];
                    float g1 = sE[r * 130 + j + 1];
                    float u0 = acc[mi][ni][half * 2];
                    float u1 = acc[mi][ni][half * 2 + 1];
                    float h0 = g0 * (1.0f / (1.0f + __expf(-g0))) * u0;
                    float h1 = g1 * (1.0f / (1.0f + __expf(-g1))) * u1;
                    __half2 hv = __floats2half2_rn(h0, h1);
                    *(__half2*)&g_hbh[(rowBase + r) * In + (size_t)n0 + j] = hv;
                }
            }
    }
}

// =============================================================================
// GEMM2: po = wt * (h W2^T).  CTA tile M=128 x N=256 out cols, K = In.
// =============================================================================
__global__ __launch_bounds__(256, 1) void k_gemm2() {
    extern __shared__ __align__(16) char smraw[];
    const int ntile = blockIdx.x, mtile = blockIdx.y;  // ntile fast (w2 L2-resident)
    if (mtile * 128 >= g_off[En]) return;
    int e = 0;
#pragma unroll
    for (int i = 0; i < En; i++) if (mtile * 128 >= g_off[i + 1]) e = i + 1;
    const int n0 = ntile * 256;
    const int tid = threadIdx.x;

    const uint32_t sb = smem_u32(smraw);
    const uint32_t sbA = sb, sbB = sb + BOFF_B;

    const int r0 = tid >> 4, sg = tid & 15;
    const int strA = In;
    const __half* pA0 = g_hbh + (size_t)(mtile * 128 + r0) * In + sg * 8;
    const __half* pB0 = g_w2h + ((size_t)e * Hn + n0 + r0) * In + sg * 8;
    const uint32_t sA0 = sbA + r0 * ROWP_B + sg * 16;
    const uint32_t sB0 = sbB + r0 * ROWP_B + sg * 16;
#define B_ADDR(q) (pB0 + (size_t)(q) * 16 * In)

    const int w = tid >> 5, lane = tid & 31;
    const int mBase = (w & 1) * 64, nBase = (w >> 1) * 64;
    const int qr = lane >> 2, qc = lane & 3;
    const int loff = ldm_lane_off(lane);

    float acc[4][8][4];
#pragma unroll
    for (int a = 0; a < 4; a++)
#pragma unroll
        for (int b = 0; b < 8; b++)
#pragma unroll
            for (int c = 0; c < 4; c++) acc[a][b][c] = 0.0f;

    GEMM_MAINLOOP(In / 128)  // 22 chunks
#undef B_ADDR

    // ---- epilogue: scale by router weight, write per-pair fp16 output --------
    const size_t rowBase = (size_t)mtile * 128;
#pragma unroll
    for (int mi = 0; mi < 4; mi++) {
#pragma unroll
        for (int half = 0; half < 2; half++) {
            int r = mBase + mi * 16 + qr + half * 8;
            float wt = g_wt[rowBase + r];
#pragma unroll
            for (int ni = 0; ni < 8; ni++) {
                int c = nBase + ni * 8 + qc * 2;
                __half2 hv = __floats2half2_rn(wt * acc[mi][ni][half * 2],
                                               wt * acc[mi][ni][half * 2 + 1]);
                *(__half2*)&g_poh[(rowBase + r) * Hn + (size_t)n0 + c] = hv;
            }
        }
    }
}

// ------------------- combine: out[t] = po[slot0] + po[slot1] ------------------
__global__ void k_combine(float* __restrict__ out) {
    int t = blockIdx.x;
    int i = threadIdx.x;  // 256 threads x 4 halves
    int s0 = g_slots[2 * t], s1 = g_slots[2 * t + 1];
    uint2 pa = *(const uint2*)&g_poh[(size_t)s0 * Hn + i * 4];
    uint2 pb = *(const uint2*)&g_poh[(size_t)s1 * Hn + i * 4];
    float2 a0 = __half22float2(*(__half2*)&pa.x), a1 = __half22float2(*(__half2*)&pa.y);
    float2 b0 = __half22float2(*(__half2*)&pb.x), b1 = __half22float2(*(__half2*)&pb.y);
    float4 o;
    o.x = a0.x + b0.x; o.y = a0.y + b0.y; o.z = a1.x + b1.x; o.w = a1.y + b1.y;
    *(float4*)&out[(size_t)t * Hn + i * 4] = o;
}

// ------------------- launcher (fork/join for conversion overlap) --------------
extern "C" void kernel_launch(void* const* d_in, const int* in_sizes, int n_in,
                              void* d_out, int out_size) {
    const float* x      = (const float*)d_in[0];
    const float* logits = (const float*)d_in[1];
    const float* w13    = (const float*)d_in[2];
    const float* w2     = (const float*)d_in[3];
    float* out = (float*)d_out;

    // host-side resources, created once (no device memory involvement)
    static cudaStream_t s1 = [] { cudaStream_t s; cudaStreamCreateWithFlags(&s, cudaStreamNonBlocking); return s; }();
    static cudaStream_t s2 = [] { cudaStream_t s; cudaStreamCreateWithFlags(&s, cudaStreamNonBlocking); return s; }();
    static cudaEvent_t eRoot = [] { cudaEvent_t e; cudaEventCreateWithFlags(&e, cudaEventDisableTiming); return e; }();
    static cudaEvent_t e13 = [] { cudaEvent_t e; cudaEventCreateWithFlags(&e, cudaEventDisableTiming); return e; }();
    static cudaEvent_t e2 = [] { cudaEvent_t e; cudaEventCreateWithFlags(&e, cudaEventDisableTiming); return e; }();

    static bool attr_set = [] {
        cudaFuncSetAttribute(k_gemm1, cudaFuncAttributeMaxDynamicSharedMemorySize, SMEM_BYTES);
        cudaFuncSetAttribute(k_gemm2, cudaFuncAttributeMaxDynamicSharedMemorySize, SMEM_BYTES);
        return true;
    }();
    (void)attr_set;

    // fork: weight conversions on side streams
    cudaEventRecord(eRoot, 0);
    cudaStreamWaitEvent(s1, eRoot, 0);
    cudaStreamWaitEvent(s2, eRoot, 0);
    k_cvtw13<<<2048, 256, 0, s1>>>(w13);
    cudaEventRecord(e13, s1);
    k_cvtw2<<<1024, 256, 0, s2>>>(w2);
    cudaEventRecord(e2, s2);

    // main chain (concurrent with conversions)
    k_init<<<68, 256>>>();
    k_router<<<Tn / 256, 256>>>(logits);
    k_off<<<1, 32>>>();
    k_scatter<<<Tn / 256, 256>>>();
    k_gather<<<MAXP, 256>>>(x);

    // join w13 before GEMM1, w2 before GEMM2
    cudaStreamWaitEvent(0, e13, 0);
    k_gemm1<<<dim3(MAXP / 128, In / 128), 256, SMEM_BYTES>>>();     // (136, 22)
    cudaStreamWaitEvent(0, e2, 0);
    k_gemm2<<<dim3(Hn / 256, MAXP / 128), 256, SMEM_BYTES>>>();     // (4, 136)
    k_combine<<<Tn, 256>>>(out);
}